// round 7
// baseline (speedup 1.0000x reference)
#include <cuda_runtime.h>
#include <cstdint>

// ---------------------------------------------------------------------------
// Problem constants
// ---------------------------------------------------------------------------
#define B_  4
#define T_  2048
#define E_  1024
#define H_  16
#define HS_ 64
#define M_  (B_ * T_)        // 8192 rows
#define F_  (4 * E_)         // 4096 ffn dim
#define EPS_ 1e-5f
#define ATT_SCALE 0.03125f   // E^-0.5 = 1/32

// ---------------------------------------------------------------------------
// Scratch (device globals; no allocation anywhere)
// ---------------------------------------------------------------------------
__device__ float g_h [(size_t)M_ * E_];   // ln output (reused for ln2)
__device__ float g_q [(size_t)M_ * E_];
__device__ float g_k [(size_t)M_ * E_];
__device__ float g_v [(size_t)M_ * E_];
__device__ float g_y [(size_t)M_ * E_];
__device__ float g_t1[(size_t)M_ * F_];   // ffn hidden
// tf32-rounded weight copies (same [K,N] layout as inputs)
__device__ float g_wq[(size_t)E_ * E_];
__device__ float g_wk[(size_t)E_ * E_];
__device__ float g_wv[(size_t)E_ * E_];
__device__ float g_wo[(size_t)E_ * E_];
__device__ float g_w1[(size_t)E_ * F_];
__device__ float g_w2[(size_t)E_ * F_];

// ---------------------------------------------------------------------------
// Helpers
// ---------------------------------------------------------------------------
__device__ __forceinline__ uint32_t smem_to_u32(const void* p) {
    uint32_t a;
    asm("{ .reg .u64 t; cvta.to.shared.u64 t, %1; cvt.u32.u64 %0, t; }"
        : "=r"(a) : "l"(p));
    return a;
}

// tf32 round-to-nearest: destination of cvt.*.tf32 is a .b32 register.
__device__ __forceinline__ float tf32r(float x) {
    uint32_t y;
    asm("cvt.rna.tf32.f32 %0, %1;" : "=r"(y) : "f"(x));
    return __uint_as_float(y);
}

__device__ __forceinline__ void cp16(uint32_t saddr, const void* g) {
    asm volatile("cp.async.cg.shared.global [%0], [%1], 16;"
                 :: "r"(saddr), "l"(g) : "memory");
}

// ---------------------------------------------------------------------------
// tf32 mma.sync GEMM: C[M,N] = A[M,K] @ B[K,N] (+ epilogue)
// Block 128x128, BK=32, 3-stage cp.async pipeline, 8 warps (2x4), 64x32/warp.
// Smem: As[128][36] (row-major), Bs[32][136].
// MODE 0: C = AB
// MODE 1: C = tf32(relu(AB + bias))
// MODE 2: C = AB + bias + res   (res may alias C; 1 owner thread per element)
// ---------------------------------------------------------------------------
#define BM 128
#define BN 128
#define BK 32
#define STAGES 3
#define AS_STRIDE 36
#define BS_STRIDE 136
#define A_ELEMS (BM * AS_STRIDE)            // 4608 floats
#define B_ELEMS (BK * BS_STRIDE)            // 4352 floats
#define STAGE_ELEMS (A_ELEMS + B_ELEMS)     // 8960 floats
#define GEMM_SMEM (STAGES * STAGE_ELEMS * 4)  // 107520 bytes

template <int MODE>
__global__ void __launch_bounds__(256)
gemm_mma(const float* __restrict__ A, const float* __restrict__ Bg,
         float* __restrict__ C, const float* __restrict__ bias,
         const float* __restrict__ res, int N, int K)
{
    extern __shared__ float smem[];
    uint32_t sbase = smem_to_u32(smem);

    int tid  = threadIdx.x;
    int lane = tid & 31;
    int wid  = tid >> 5;
    int bm = blockIdx.y * BM;
    int bn = blockIdx.x * BN;
    int wm = (wid >> 2) * 64;   // warp m offset within block
    int wn = (wid & 3) * 32;    // warp n offset within block
    int lr = lane >> 2;         // groupID (0..7)
    int lc = lane & 3;          // threadID_in_group (0..3)

    float acc[4][4][4];
#pragma unroll
    for (int mt = 0; mt < 4; mt++)
#pragma unroll
        for (int nt = 0; nt < 4; nt++)
#pragma unroll
            for (int r = 0; r < 4; r++) acc[mt][nt][r] = 0.f;

    const int KIT = K / BK;

    // per-thread cp.async coordinates (4 chunks A + 4 chunks B per stage)
    int a_r[4], a_c[4], b_r[4], b_c[4];
#pragma unroll
    for (int w = 0; w < 4; w++) {
        int chunk = tid + w * 256;
        a_r[w] = chunk >> 3;  a_c[w] = (chunk & 7) * 4;   // A: 128 rows x 8 chunks
        b_r[w] = chunk >> 5;  b_c[w] = (chunk & 31) * 4;  // B: 32 rows x 32 chunks
    }

    // ---- prologue: prefetch stages 0..STAGES-2 ----
#pragma unroll
    for (int s = 0; s < STAGES - 1; s++) {
        uint32_t sa = sbase + (uint32_t)(s * STAGE_ELEMS) * 4;
        uint32_t sb = sa + (uint32_t)A_ELEMS * 4;
        int k0 = s * BK;
#pragma unroll
        for (int w = 0; w < 4; w++)
            cp16(sa + (uint32_t)(a_r[w] * AS_STRIDE + a_c[w]) * 4,
                 A + (size_t)(bm + a_r[w]) * K + k0 + a_c[w]);
#pragma unroll
        for (int w = 0; w < 4; w++)
            cp16(sb + (uint32_t)(b_r[w] * BS_STRIDE + b_c[w]) * 4,
                 Bg + (size_t)(k0 + b_r[w]) * N + bn + b_c[w]);
        asm volatile("cp.async.commit_group;" ::: "memory");
    }

    // ---- mainloop ----
    for (int it = 0; it < KIT; it++) {
        asm volatile("cp.async.wait_group %0;" :: "n"(STAGES - 2) : "memory");
        __syncthreads();

        // prefetch stage it+STAGES-1 (overwrites stage consumed at it-1)
        int pf = it + STAGES - 1;
        if (pf < KIT) {
            int s = pf % STAGES;
            uint32_t sa = sbase + (uint32_t)(s * STAGE_ELEMS) * 4;
            uint32_t sb = sa + (uint32_t)A_ELEMS * 4;
            int k0 = pf * BK;
#pragma unroll
            for (int w = 0; w < 4; w++)
                cp16(sa + (uint32_t)(a_r[w] * AS_STRIDE + a_c[w]) * 4,
                     A + (size_t)(bm + a_r[w]) * K + k0 + a_c[w]);
#pragma unroll
            for (int w = 0; w < 4; w++)
                cp16(sb + (uint32_t)(b_r[w] * BS_STRIDE + b_c[w]) * 4,
                     Bg + (size_t)(k0 + b_r[w]) * N + bn + b_c[w]);
        }
        asm volatile("cp.async.commit_group;" ::: "memory");

        // compute on stage it%STAGES
        const float* As = smem + (it % STAGES) * STAGE_ELEMS;
        const float* Bs = As + A_ELEMS;
#pragma unroll
        for (int ks = 0; ks < 4; ks++) {
            int kb = ks * 8;
            uint32_t a[4][4], b[4][2];
#pragma unroll
            for (int mt = 0; mt < 4; mt++) {
                int r = wm + mt * 16 + lr;
                a[mt][0] = __float_as_uint(As[r * AS_STRIDE + kb + lc]);
                a[mt][1] = __float_as_uint(As[(r + 8) * AS_STRIDE + kb + lc]);
                a[mt][2] = __float_as_uint(As[r * AS_STRIDE + kb + lc + 4]);
                a[mt][3] = __float_as_uint(As[(r + 8) * AS_STRIDE + kb + lc + 4]);
            }
#pragma unroll
            for (int nt = 0; nt < 4; nt++) {
                int c = wn + nt * 8 + lr;
                b[nt][0] = __float_as_uint(Bs[(kb + lc) * BS_STRIDE + c]);
                b[nt][1] = __float_as_uint(Bs[(kb + lc + 4) * BS_STRIDE + c]);
            }
#pragma unroll
            for (int mt = 0; mt < 4; mt++)
#pragma unroll
                for (int nt = 0; nt < 4; nt++)
                    asm volatile(
                        "mma.sync.aligned.m16n8k8.row.col.f32.tf32.tf32.f32 "
                        "{%0,%1,%2,%3}, {%4,%5,%6,%7}, {%8,%9}, {%0,%1,%2,%3};"
                        : "+f"(acc[mt][nt][0]), "+f"(acc[mt][nt][1]),
                          "+f"(acc[mt][nt][2]), "+f"(acc[mt][nt][3])
                        : "r"(a[mt][0]), "r"(a[mt][1]), "r"(a[mt][2]), "r"(a[mt][3]),
                          "r"(b[nt][0]), "r"(b[nt][1]));
        }
    }

    // ---- epilogue ----
#pragma unroll
    for (int mt = 0; mt < 4; mt++) {
#pragma unroll
        for (int nt = 0; nt < 4; nt++) {
            int r0  = bm + wm + mt * 16 + lr;
            int col = bn + wn + nt * 8 + lc * 2;
            float2 v0 = make_float2(acc[mt][nt][0], acc[mt][nt][1]);
            float2 v1 = make_float2(acc[mt][nt][2], acc[mt][nt][3]);
            size_t o0 = (size_t)r0 * N + col;
            size_t o1 = o0 + (size_t)8 * N;
            if (MODE == 1) {
                float2 b2v = *(const float2*)(bias + col);
                v0.x = tf32r(fmaxf(v0.x + b2v.x, 0.f));
                v0.y = tf32r(fmaxf(v0.y + b2v.y, 0.f));
                v1.x = tf32r(fmaxf(v1.x + b2v.x, 0.f));
                v1.y = tf32r(fmaxf(v1.y + b2v.y, 0.f));
            } else if (MODE == 2) {
                float2 b2v = *(const float2*)(bias + col);
                float2 r2a = *(const float2*)(res + o0);
                float2 r2b = *(const float2*)(res + o1);
                v0.x += b2v.x + r2a.x;  v0.y += b2v.y + r2a.y;
                v1.x += b2v.x + r2b.x;  v1.y += b2v.y + r2b.y;
            }
            *(float2*)(C + o0) = v0;
            *(float2*)(C + o1) = v1;
        }
    }
}

// ---------------------------------------------------------------------------
// Elementwise tf32 rounding of weights (float4)
// ---------------------------------------------------------------------------
__global__ __launch_bounds__(256) void round_tf32(
    const float* __restrict__ w, float* __restrict__ o, int n4)
{
    int i = blockIdx.x * blockDim.x + threadIdx.x;
    if (i < n4) {
        float4 v = ((const float4*)w)[i];
        v.x = tf32r(v.x); v.y = tf32r(v.y);
        v.z = tf32r(v.z); v.w = tf32r(v.w);
        ((float4*)o)[i] = v;
    }
}

// ---------------------------------------------------------------------------
// LayerNorm (output tf32-rounded; feeds GEMMs only)
// ---------------------------------------------------------------------------
__global__ __launch_bounds__(256) void ln_kernel(
    const float* __restrict__ x, const float* __restrict__ w,
    float* __restrict__ out)
{
    int row = blockIdx.x;
    int tid = threadIdx.x;
    const float4* xr = (const float4*)(x + (size_t)row * E_);
    float4 v = xr[tid];
    float s  = v.x + v.y + v.z + v.w;
    float ss = v.x * v.x + v.y * v.y + v.z * v.z + v.w * v.w;
#pragma unroll
    for (int o = 16; o > 0; o >>= 1) {
        s  += __shfl_xor_sync(0xffffffffu, s, o);
        ss += __shfl_xor_sync(0xffffffffu, ss, o);
    }
    __shared__ float rs[8], rss[8];
    if ((tid & 31) == 0) { rs[tid >> 5] = s; rss[tid >> 5] = ss; }
    __syncthreads();
    float ts = 0.f, tss = 0.f;
#pragma unroll
    for (int i = 0; i < 8; i++) { ts += rs[i]; tss += rss[i]; }
    float mean = ts * (1.f / E_);
    float var  = tss * (1.f / E_) - mean * mean;
    float inv  = rsqrtf(var + EPS_);
    float4 wv = ((const float4*)w)[tid];
    float4 o4;
    o4.x = tf32r((v.x - mean) * inv * wv.x);
    o4.y = tf32r((v.y - mean) * inv * wv.y);
    o4.z = tf32r((v.z - mean) * inv * wv.z);
    o4.w = tf32r((v.w - mean) * inv * wv.w);
    ((float4*)(out + (size_t)row * E_))[tid] = o4;
}

// ---------------------------------------------------------------------------
// Flash-style causal attention (fp32 SIMT), output tf32-rounded
// ---------------------------------------------------------------------------
__global__ __launch_bounds__(128, 1) void attn_kernel(
    const float* __restrict__ Q, const float* __restrict__ K,
    const float* __restrict__ V, float* __restrict__ O)
{
    __shared__ float Ks[64][64];
    __shared__ float Vs[64][64];

    int tid = threadIdx.x;
    int bx  = blockIdx.x;
    int bh  = blockIdx.y;
    int b   = bh >> 4;
    int h   = bh & 15;

    int qi = bx * 128 + tid;
    size_t qbase = ((size_t)(b * T_ + qi) * E_) + h * HS_;

    float q[HS_];
#pragma unroll
    for (int d4 = 0; d4 < 16; d4++) {
        float4 qq = *(const float4*)(Q + qbase + d4 * 4);
        q[d4 * 4 + 0] = qq.x * ATT_SCALE;
        q[d4 * 4 + 1] = qq.y * ATT_SCALE;
        q[d4 * 4 + 2] = qq.z * ATT_SCALE;
        q[d4 * 4 + 3] = qq.w * ATT_SCALE;
    }

    float m = -1e30f, l = 0.f;
    float acc[HS_];
#pragma unroll
    for (int d = 0; d < HS_; d++) acc[d] = 0.f;

    int ntiles = (bx + 1) * 2;
    for (int kv = 0; kv < ntiles; kv++) {
        __syncthreads();
        for (int i = tid; i < 64 * 16; i += 128) {
            int r = i >> 4;
            int c4 = i & 15;
            size_t gk = ((size_t)(b * T_ + kv * 64 + r) * E_) + h * HS_ + c4 * 4;
            *(float4*)&Ks[r][c4 * 4] = *(const float4*)(K + gk);
            *(float4*)&Vs[r][c4 * 4] = *(const float4*)(V + gk);
        }
        __syncthreads();

        int rel = qi - kv * 64;
        if (rel >= 0) {
            int jmax = rel < 63 ? rel : 63;
            for (int c0 = 0; c0 <= jmax; c0 += 16) {
                float sc[16];
                float cm = -1e30f;
#pragma unroll
                for (int jj = 0; jj < 16; jj++) {
                    int j = c0 + jj;
                    float d = 0.f;
#pragma unroll
                    for (int d4 = 0; d4 < 16; d4++) {
                        float4 kk = *(const float4*)&Ks[j][d4 * 4];
                        d += q[d4 * 4 + 0] * kk.x;
                        d += q[d4 * 4 + 1] * kk.y;
                        d += q[d4 * 4 + 2] * kk.z;
                        d += q[d4 * 4 + 3] * kk.w;
                    }
                    sc[jj] = (j <= jmax) ? d : -1e30f;
                    cm = fmaxf(cm, sc[jj]);
                }
                float mn = fmaxf(m, cm);
                float corr = __expf(m - mn);
                l *= corr;
#pragma unroll
                for (int d = 0; d < HS_; d++) acc[d] *= corr;
                m = mn;
#pragma unroll
                for (int jj = 0; jj < 16; jj++) {
                    float p = __expf(sc[jj] - mn);
                    l += p;
                    int j = c0 + jj;
#pragma unroll
                    for (int d4 = 0; d4 < 16; d4++) {
                        float4 vv = *(const float4*)&Vs[j][d4 * 4];
                        acc[d4 * 4 + 0] += p * vv.x;
                        acc[d4 * 4 + 1] += p * vv.y;
                        acc[d4 * 4 + 2] += p * vv.z;
                        acc[d4 * 4 + 3] += p * vv.w;
                    }
                }
            }
        }
    }

    float invl = 1.f / l;
#pragma unroll
    for (int d4 = 0; d4 < 16; d4++) {
        float4 o4;
        o4.x = tf32r(acc[d4 * 4 + 0] * invl);
        o4.y = tf32r(acc[d4 * 4 + 1] * invl);
        o4.z = tf32r(acc[d4 * 4 + 2] * invl);
        o4.w = tf32r(acc[d4 * 4 + 3] * invl);
        *(float4*)(O + qbase + d4 * 4) = o4;
    }
}

// ---------------------------------------------------------------------------
// Launch
// ---------------------------------------------------------------------------
extern "C" void kernel_launch(void* const* d_in, const int* in_sizes, int n_in,
                              void* d_out, int out_size)
{
    const float* x    = (const float*)d_in[0];
    const float* Wq   = (const float*)d_in[1];
    const float* Wk   = (const float*)d_in[2];
    const float* Wv   = (const float*)d_in[3];
    const float* Wo   = (const float*)d_in[4];
    const float* bo   = (const float*)d_in[5];
    const float* ln1w = (const float*)d_in[6];
    const float* ln2w = (const float*)d_in[7];
    const float* W1   = (const float*)d_in[8];
    const float* b1   = (const float*)d_in[9];
    const float* W2   = (const float*)d_in[10];
    const float* b2   = (const float*)d_in[11];
    float* out = (float*)d_out;

    float *h, *q, *k, *v, *y, *t1, *wq, *wk, *wv, *wo, *w1, *w2;
    cudaGetSymbolAddress((void**)&h,  g_h);
    cudaGetSymbolAddress((void**)&q,  g_q);
    cudaGetSymbolAddress((void**)&k,  g_k);
    cudaGetSymbolAddress((void**)&v,  g_v);
    cudaGetSymbolAddress((void**)&y,  g_y);
    cudaGetSymbolAddress((void**)&t1, g_t1);
    cudaGetSymbolAddress((void**)&wq, g_wq);
    cudaGetSymbolAddress((void**)&wk, g_wk);
    cudaGetSymbolAddress((void**)&wv, g_wv);
    cudaGetSymbolAddress((void**)&wo, g_wo);
    cudaGetSymbolAddress((void**)&w1, g_w1);
    cudaGetSymbolAddress((void**)&w2, g_w2);

    cudaFuncSetAttribute(gemm_mma<0>, cudaFuncAttributeMaxDynamicSharedMemorySize, GEMM_SMEM);
    cudaFuncSetAttribute(gemm_mma<1>, cudaFuncAttributeMaxDynamicSharedMemorySize, GEMM_SMEM);
    cudaFuncSetAttribute(gemm_mma<2>, cudaFuncAttributeMaxDynamicSharedMemorySize, GEMM_SMEM);

    // tf32-round the weights (RNA; makes HMMA truncation exact)
    int nE = E_ * E_ / 4, nF = E_ * F_ / 4;
    round_tf32<<<(nE + 255) / 256, 256>>>(Wq, wq, nE);
    round_tf32<<<(nE + 255) / 256, 256>>>(Wk, wk, nE);
    round_tf32<<<(nE + 255) / 256, 256>>>(Wv, wv, nE);
    round_tf32<<<(nE + 255) / 256, 256>>>(Wo, wo, nE);
    round_tf32<<<(nF + 255) / 256, 256>>>(W1, w1, nF);
    round_tf32<<<(nF + 255) / 256, 256>>>(W2, w2, nF);

    dim3 gE(E_ / BN, M_ / BM);   // 8 x 64
    dim3 gF(F_ / BN, M_ / BM);   // 32 x 64

    // h = LN(x)
    ln_kernel<<<M_, 256>>>(x, ln1w, h);
    // q,k,v = h @ W{q,k,v}
    gemm_mma<0><<<gE, 256, GEMM_SMEM>>>(h, wq, q, nullptr, nullptr, E_, E_);
    gemm_mma<0><<<gE, 256, GEMM_SMEM>>>(h, wk, k, nullptr, nullptr, E_, E_);
    gemm_mma<0><<<gE, 256, GEMM_SMEM>>>(h, wv, v, nullptr, nullptr, E_, E_);
    // y = causal_attn(q,k,v)
    attn_kernel<<<dim3(T_ / 128, B_ * H_), 128>>>(q, k, v, y);
    // x2 = x + y @ Wo + bo
    gemm_mma<2><<<gE, 256, GEMM_SMEM>>>(y, wo, out, bo, x, E_, E_);
    // h = LN(x2)
    ln_kernel<<<M_, 256>>>(out, ln2w, h);
    // t1 = relu(h @ W1 + b1)
    gemm_mma<1><<<gF, 256, GEMM_SMEM>>>(h, w1, t1, b1, nullptr, F_, E_);
    // out = x2 + t1 @ W2 + b2
    gemm_mma<2><<<gE, 256, GEMM_SMEM>>>(t1, w2, out, b2, out, E_, F_);
}

// round 8
// speedup vs baseline: 1.0041x; 1.0041x over previous
#include <cuda_runtime.h>
#include <cstdint>

// ---------------------------------------------------------------------------
// Problem constants
// ---------------------------------------------------------------------------
#define B_  4
#define T_  2048
#define E_  1024
#define H_  16
#define HS_ 64
#define M_  (B_ * T_)        // 8192 rows
#define F_  (4 * E_)         // 4096 ffn dim
#define EPS_ 1e-5f
#define ATT_SCALE 0.03125f   // E^-0.5 = 1/32

// ---------------------------------------------------------------------------
// Scratch (device globals; no allocation anywhere)
// ---------------------------------------------------------------------------
__device__ float g_h [(size_t)M_ * E_];   // ln output (reused for ln2)
__device__ float g_q [(size_t)M_ * E_];
__device__ float g_k [(size_t)M_ * E_];
__device__ float g_v [(size_t)M_ * E_];
__device__ float g_y [(size_t)M_ * E_];
__device__ float g_t1[(size_t)M_ * F_];   // ffn hidden
// tf32-rounded weight copies (same [K,N] layout as inputs)
__device__ float g_wq[(size_t)E_ * E_];
__device__ float g_wk[(size_t)E_ * E_];
__device__ float g_wv[(size_t)E_ * E_];
__device__ float g_wo[(size_t)E_ * E_];
__device__ float g_w1[(size_t)E_ * F_];
__device__ float g_w2[(size_t)E_ * F_];

// ---------------------------------------------------------------------------
// Helpers
// ---------------------------------------------------------------------------
__device__ __forceinline__ uint32_t smem_to_u32(const void* p) {
    uint32_t a;
    asm("{ .reg .u64 t; cvta.to.shared.u64 t, %1; cvt.u32.u64 %0, t; }"
        : "=r"(a) : "l"(p));
    return a;
}

// tf32 round-to-nearest: destination of cvt.*.tf32 is a .b32 register.
__device__ __forceinline__ float tf32r(float x) {
    uint32_t y;
    asm("cvt.rna.tf32.f32 %0, %1;" : "=r"(y) : "f"(x));
    return __uint_as_float(y);
}

__device__ __forceinline__ void cp16(uint32_t saddr, const void* g) {
    asm volatile("cp.async.cg.shared.global [%0], [%1], 16;"
                 :: "r"(saddr), "l"(g) : "memory");
}

// ---------------------------------------------------------------------------
// tf32 mma.sync GEMM: C[M,N] = A[M,K] @ B[K,N] (+ epilogue)
// Block 128x128, BK=32, 3-stage cp.async pipeline, 8 warps (2x4), 64x32/warp.
// Smem: As[128][36] (row-major), Bs[32][136].
// MODE 0: C = AB
// MODE 1: C = tf32(relu(AB + bias))
// MODE 2: C = AB + bias + res   (res may alias C; 1 owner thread per element)
// ---------------------------------------------------------------------------
#define BM 128
#define BN 128
#define BK 32
#define STAGES 3
#define AS_STRIDE 36
#define BS_STRIDE 136
#define A_ELEMS (BM * AS_STRIDE)            // 4608 floats
#define B_ELEMS (BK * BS_STRIDE)            // 4352 floats
#define STAGE_ELEMS (A_ELEMS + B_ELEMS)     // 8960 floats
#define GEMM_SMEM (STAGES * STAGE_ELEMS * 4)  // 107520 bytes

template <int MODE>
__global__ void __launch_bounds__(256)
gemm_mma(const float* __restrict__ A, const float* __restrict__ Bg,
         float* __restrict__ C, const float* __restrict__ bias,
         const float* __restrict__ res, int N, int K)
{
    extern __shared__ float smem[];
    uint32_t sbase = smem_to_u32(smem);

    int tid  = threadIdx.x;
    int lane = tid & 31;
    int wid  = tid >> 5;
    int bm = blockIdx.y * BM;
    int bn = blockIdx.x * BN;
    int wm = (wid >> 2) * 64;   // warp m offset within block
    int wn = (wid & 3) * 32;    // warp n offset within block
    int lr = lane >> 2;         // groupID (0..7)
    int lc = lane & 3;          // threadID_in_group (0..3)

    float acc[4][4][4];
#pragma unroll
    for (int mt = 0; mt < 4; mt++)
#pragma unroll
        for (int nt = 0; nt < 4; nt++)
#pragma unroll
            for (int r = 0; r < 4; r++) acc[mt][nt][r] = 0.f;

    const int KIT = K / BK;

    // per-thread cp.async coordinates (4 chunks A + 4 chunks B per stage)
    int a_r[4], a_c[4], b_r[4], b_c[4];
#pragma unroll
    for (int w = 0; w < 4; w++) {
        int chunk = tid + w * 256;
        a_r[w] = chunk >> 3;  a_c[w] = (chunk & 7) * 4;   // A: 128 rows x 8 chunks
        b_r[w] = chunk >> 5;  b_c[w] = (chunk & 31) * 4;  // B: 32 rows x 32 chunks
    }

    // ---- prologue: prefetch stages 0..STAGES-2 ----
#pragma unroll
    for (int s = 0; s < STAGES - 1; s++) {
        uint32_t sa = sbase + (uint32_t)(s * STAGE_ELEMS) * 4;
        uint32_t sb = sa + (uint32_t)A_ELEMS * 4;
        int k0 = s * BK;
#pragma unroll
        for (int w = 0; w < 4; w++)
            cp16(sa + (uint32_t)(a_r[w] * AS_STRIDE + a_c[w]) * 4,
                 A + (size_t)(bm + a_r[w]) * K + k0 + a_c[w]);
#pragma unroll
        for (int w = 0; w < 4; w++)
            cp16(sb + (uint32_t)(b_r[w] * BS_STRIDE + b_c[w]) * 4,
                 Bg + (size_t)(k0 + b_r[w]) * N + bn + b_c[w]);
        asm volatile("cp.async.commit_group;" ::: "memory");
    }

    // ---- mainloop ----
    for (int it = 0; it < KIT; it++) {
        asm volatile("cp.async.wait_group %0;" :: "n"(STAGES - 2) : "memory");
        __syncthreads();

        // prefetch stage it+STAGES-1 (overwrites stage consumed at it-1)
        int pf = it + STAGES - 1;
        if (pf < KIT) {
            int s = pf % STAGES;
            uint32_t sa = sbase + (uint32_t)(s * STAGE_ELEMS) * 4;
            uint32_t sb = sa + (uint32_t)A_ELEMS * 4;
            int k0 = pf * BK;
#pragma unroll
            for (int w = 0; w < 4; w++)
                cp16(sa + (uint32_t)(a_r[w] * AS_STRIDE + a_c[w]) * 4,
                     A + (size_t)(bm + a_r[w]) * K + k0 + a_c[w]);
#pragma unroll
            for (int w = 0; w < 4; w++)
                cp16(sb + (uint32_t)(b_r[w] * BS_STRIDE + b_c[w]) * 4,
                     Bg + (size_t)(k0 + b_r[w]) * N + bn + b_c[w]);
        }
        asm volatile("cp.async.commit_group;" ::: "memory");

        // compute on stage it%STAGES
        const float* As = smem + (it % STAGES) * STAGE_ELEMS;
        const float* Bs = As + A_ELEMS;
#pragma unroll
        for (int ks = 0; ks < 4; ks++) {
            int kb = ks * 8;
            uint32_t a[4][4], b[4][2];
#pragma unroll
            for (int mt = 0; mt < 4; mt++) {
                int r = wm + mt * 16 + lr;
                a[mt][0] = __float_as_uint(As[r * AS_STRIDE + kb + lc]);
                a[mt][1] = __float_as_uint(As[(r + 8) * AS_STRIDE + kb + lc]);
                a[mt][2] = __float_as_uint(As[r * AS_STRIDE + kb + lc + 4]);
                a[mt][3] = __float_as_uint(As[(r + 8) * AS_STRIDE + kb + lc + 4]);
            }
#pragma unroll
            for (int nt = 0; nt < 4; nt++) {
                int c = wn + nt * 8 + lr;
                b[nt][0] = __float_as_uint(Bs[(kb + lc) * BS_STRIDE + c]);
                b[nt][1] = __float_as_uint(Bs[(kb + lc + 4) * BS_STRIDE + c]);
            }
#pragma unroll
            for (int mt = 0; mt < 4; mt++)
#pragma unroll
                for (int nt = 0; nt < 4; nt++)
                    asm volatile(
                        "mma.sync.aligned.m16n8k8.row.col.f32.tf32.tf32.f32 "
                        "{%0,%1,%2,%3}, {%4,%5,%6,%7}, {%8,%9}, {%0,%1,%2,%3};"
                        : "+f"(acc[mt][nt][0]), "+f"(acc[mt][nt][1]),
                          "+f"(acc[mt][nt][2]), "+f"(acc[mt][nt][3])
                        : "r"(a[mt][0]), "r"(a[mt][1]), "r"(a[mt][2]), "r"(a[mt][3]),
                          "r"(b[nt][0]), "r"(b[nt][1]));
        }
    }

    // ---- epilogue ----
#pragma unroll
    for (int mt = 0; mt < 4; mt++) {
#pragma unroll
        for (int nt = 0; nt < 4; nt++) {
            int r0  = bm + wm + mt * 16 + lr;
            int col = bn + wn + nt * 8 + lc * 2;
            float2 v0 = make_float2(acc[mt][nt][0], acc[mt][nt][1]);
            float2 v1 = make_float2(acc[mt][nt][2], acc[mt][nt][3]);
            size_t o0 = (size_t)r0 * N + col;
            size_t o1 = o0 + (size_t)8 * N;
            if (MODE == 1) {
                float2 b2v = *(const float2*)(bias + col);
                v0.x = tf32r(fmaxf(v0.x + b2v.x, 0.f));
                v0.y = tf32r(fmaxf(v0.y + b2v.y, 0.f));
                v1.x = tf32r(fmaxf(v1.x + b2v.x, 0.f));
                v1.y = tf32r(fmaxf(v1.y + b2v.y, 0.f));
            } else if (MODE == 2) {
                float2 b2v = *(const float2*)(bias + col);
                float2 r2a = *(const float2*)(res + o0);
                float2 r2b = *(const float2*)(res + o1);
                v0.x += b2v.x + r2a.x;  v0.y += b2v.y + r2a.y;
                v1.x += b2v.x + r2b.x;  v1.y += b2v.y + r2b.y;
            }
            *(float2*)(C + o0) = v0;
            *(float2*)(C + o1) = v1;
        }
    }
}

// ---------------------------------------------------------------------------
// Elementwise tf32 rounding of weights (float4)
// ---------------------------------------------------------------------------
__global__ __launch_bounds__(256) void round_tf32(
    const float* __restrict__ w, float* __restrict__ o, int n4)
{
    int i = blockIdx.x * blockDim.x + threadIdx.x;
    if (i < n4) {
        float4 v = ((const float4*)w)[i];
        v.x = tf32r(v.x); v.y = tf32r(v.y);
        v.z = tf32r(v.z); v.w = tf32r(v.w);
        ((float4*)o)[i] = v;
    }
}

// ---------------------------------------------------------------------------
// LayerNorm (output tf32-rounded; feeds GEMMs only)
// ---------------------------------------------------------------------------
__global__ __launch_bounds__(256) void ln_kernel(
    const float* __restrict__ x, const float* __restrict__ w,
    float* __restrict__ out)
{
    int row = blockIdx.x;
    int tid = threadIdx.x;
    const float4* xr = (const float4*)(x + (size_t)row * E_);
    float4 v = xr[tid];
    float s  = v.x + v.y + v.z + v.w;
    float ss = v.x * v.x + v.y * v.y + v.z * v.z + v.w * v.w;
#pragma unroll
    for (int o = 16; o > 0; o >>= 1) {
        s  += __shfl_xor_sync(0xffffffffu, s, o);
        ss += __shfl_xor_sync(0xffffffffu, ss, o);
    }
    __shared__ float rs[8], rss[8];
    if ((tid & 31) == 0) { rs[tid >> 5] = s; rss[tid >> 5] = ss; }
    __syncthreads();
    float ts = 0.f, tss = 0.f;
#pragma unroll
    for (int i = 0; i < 8; i++) { ts += rs[i]; tss += rss[i]; }
    float mean = ts * (1.f / E_);
    float var  = tss * (1.f / E_) - mean * mean;
    float inv  = rsqrtf(var + EPS_);
    float4 wv = ((const float4*)w)[tid];
    float4 o4;
    o4.x = tf32r((v.x - mean) * inv * wv.x);
    o4.y = tf32r((v.y - mean) * inv * wv.y);
    o4.z = tf32r((v.z - mean) * inv * wv.z);
    o4.w = tf32r((v.w - mean) * inv * wv.w);
    ((float4*)(out + (size_t)row * E_))[tid] = o4;
}

// ---------------------------------------------------------------------------
// Flash-style causal attention (fp32 SIMT), output tf32-rounded
// ---------------------------------------------------------------------------
__global__ __launch_bounds__(128, 1) void attn_kernel(
    const float* __restrict__ Q, const float* __restrict__ K,
    const float* __restrict__ V, float* __restrict__ O)
{
    __shared__ float Ks[64][64];
    __shared__ float Vs[64][64];

    int tid = threadIdx.x;
    int bx  = blockIdx.x;
    int bh  = blockIdx.y;
    int b   = bh >> 4;
    int h   = bh & 15;

    int qi = bx * 128 + tid;
    size_t qbase = ((size_t)(b * T_ + qi) * E_) + h * HS_;

    float q[HS_];
#pragma unroll
    for (int d4 = 0; d4 < 16; d4++) {
        float4 qq = *(const float4*)(Q + qbase + d4 * 4);
        q[d4 * 4 + 0] = qq.x * ATT_SCALE;
        q[d4 * 4 + 1] = qq.y * ATT_SCALE;
        q[d4 * 4 + 2] = qq.z * ATT_SCALE;
        q[d4 * 4 + 3] = qq.w * ATT_SCALE;
    }

    float m = -1e30f, l = 0.f;
    float acc[HS_];
#pragma unroll
    for (int d = 0; d < HS_; d++) acc[d] = 0.f;

    int ntiles = (bx + 1) * 2;
    for (int kv = 0; kv < ntiles; kv++) {
        __syncthreads();
        for (int i = tid; i < 64 * 16; i += 128) {
            int r = i >> 4;
            int c4 = i & 15;
            size_t gk = ((size_t)(b * T_ + kv * 64 + r) * E_) + h * HS_ + c4 * 4;
            *(float4*)&Ks[r][c4 * 4] = *(const float4*)(K + gk);
            *(float4*)&Vs[r][c4 * 4] = *(const float4*)(V + gk);
        }
        __syncthreads();

        int rel = qi - kv * 64;
        if (rel >= 0) {
            int jmax = rel < 63 ? rel : 63;
            for (int c0 = 0; c0 <= jmax; c0 += 16) {
                float sc[16];
                float cm = -1e30f;
#pragma unroll
                for (int jj = 0; jj < 16; jj++) {
                    int j = c0 + jj;
                    float d = 0.f;
#pragma unroll
                    for (int d4 = 0; d4 < 16; d4++) {
                        float4 kk = *(const float4*)&Ks[j][d4 * 4];
                        d += q[d4 * 4 + 0] * kk.x;
                        d += q[d4 * 4 + 1] * kk.y;
                        d += q[d4 * 4 + 2] * kk.z;
                        d += q[d4 * 4 + 3] * kk.w;
                    }
                    sc[jj] = (j <= jmax) ? d : -1e30f;
                    cm = fmaxf(cm, sc[jj]);
                }
                float mn = fmaxf(m, cm);
                float corr = __expf(m - mn);
                l *= corr;
#pragma unroll
                for (int d = 0; d < HS_; d++) acc[d] *= corr;
                m = mn;
#pragma unroll
                for (int jj = 0; jj < 16; jj++) {
                    float p = __expf(sc[jj] - mn);
                    l += p;
                    int j = c0 + jj;
#pragma unroll
                    for (int d4 = 0; d4 < 16; d4++) {
                        float4 vv = *(const float4*)&Vs[j][d4 * 4];
                        acc[d4 * 4 + 0] += p * vv.x;
                        acc[d4 * 4 + 1] += p * vv.y;
                        acc[d4 * 4 + 2] += p * vv.z;
                        acc[d4 * 4 + 3] += p * vv.w;
                    }
                }
            }
        }
    }

    float invl = 1.f / l;
#pragma unroll
    for (int d4 = 0; d4 < 16; d4++) {
        float4 o4;
        o4.x = tf32r(acc[d4 * 4 + 0] * invl);
        o4.y = tf32r(acc[d4 * 4 + 1] * invl);
        o4.z = tf32r(acc[d4 * 4 + 2] * invl);
        o4.w = tf32r(acc[d4 * 4 + 3] * invl);
        *(float4*)(O + qbase + d4 * 4) = o4;
    }
}

// ---------------------------------------------------------------------------
// Launch
// ---------------------------------------------------------------------------
extern "C" void kernel_launch(void* const* d_in, const int* in_sizes, int n_in,
                              void* d_out, int out_size)
{
    const float* x    = (const float*)d_in[0];
    const float* Wq   = (const float*)d_in[1];
    const float* Wk   = (const float*)d_in[2];
    const float* Wv   = (const float*)d_in[3];
    const float* Wo   = (const float*)d_in[4];
    const float* bo   = (const float*)d_in[5];
    const float* ln1w = (const float*)d_in[6];
    const float* ln2w = (const float*)d_in[7];
    const float* W1   = (const float*)d_in[8];
    const float* b1   = (const float*)d_in[9];
    const float* W2   = (const float*)d_in[10];
    const float* b2   = (const float*)d_in[11];
    float* out = (float*)d_out;

    float *h, *q, *k, *v, *y, *t1, *wq, *wk, *wv, *wo, *w1, *w2;
    cudaGetSymbolAddress((void**)&h,  g_h);
    cudaGetSymbolAddress((void**)&q,  g_q);
    cudaGetSymbolAddress((void**)&k,  g_k);
    cudaGetSymbolAddress((void**)&v,  g_v);
    cudaGetSymbolAddress((void**)&y,  g_y);
    cudaGetSymbolAddress((void**)&t1, g_t1);
    cudaGetSymbolAddress((void**)&wq, g_wq);
    cudaGetSymbolAddress((void**)&wk, g_wk);
    cudaGetSymbolAddress((void**)&wv, g_wv);
    cudaGetSymbolAddress((void**)&wo, g_wo);
    cudaGetSymbolAddress((void**)&w1, g_w1);
    cudaGetSymbolAddress((void**)&w2, g_w2);

    cudaFuncSetAttribute(gemm_mma<0>, cudaFuncAttributeMaxDynamicSharedMemorySize, GEMM_SMEM);
    cudaFuncSetAttribute(gemm_mma<1>, cudaFuncAttributeMaxDynamicSharedMemorySize, GEMM_SMEM);
    cudaFuncSetAttribute(gemm_mma<2>, cudaFuncAttributeMaxDynamicSharedMemorySize, GEMM_SMEM);

    // tf32-round the weights (RNA; makes HMMA truncation exact)
    int nE = E_ * E_ / 4, nF = E_ * F_ / 4;
    round_tf32<<<(nE + 255) / 256, 256>>>(Wq, wq, nE);
    round_tf32<<<(nE + 255) / 256, 256>>>(Wk, wk, nE);
    round_tf32<<<(nE + 255) / 256, 256>>>(Wv, wv, nE);
    round_tf32<<<(nE + 255) / 256, 256>>>(Wo, wo, nE);
    round_tf32<<<(nF + 255) / 256, 256>>>(W1, w1, nF);
    round_tf32<<<(nF + 255) / 256, 256>>>(W2, w2, nF);

    dim3 gE(E_ / BN, M_ / BM);   // 8 x 64
    dim3 gF(F_ / BN, M_ / BM);   // 32 x 64

    // h = LN(x)
    ln_kernel<<<M_, 256>>>(x, ln1w, h);
    // q,k,v = h @ W{q,k,v}
    gemm_mma<0><<<gE, 256, GEMM_SMEM>>>(h, wq, q, nullptr, nullptr, E_, E_);
    gemm_mma<0><<<gE, 256, GEMM_SMEM>>>(h, wk, k, nullptr, nullptr, E_, E_);
    gemm_mma<0><<<gE, 256, GEMM_SMEM>>>(h, wv, v, nullptr, nullptr, E_, E_);
    // y = causal_attn(q,k,v)
    attn_kernel<<<dim3(T_ / 128, B_ * H_), 128>>>(q, k, v, y);
    // x2 = x + y @ Wo + bo
    gemm_mma<2><<<gE, 256, GEMM_SMEM>>>(y, wo, out, bo, x, E_, E_);
    // h = LN(x2)
    ln_kernel<<<M_, 256>>>(out, ln2w, h);
    // t1 = relu(h @ W1 + b1)
    gemm_mma<1><<<gF, 256, GEMM_SMEM>>>(h, w1, t1, b1, nullptr, F_, E_);
    // out = x2 + t1 @ W2 + b2
    gemm_mma<2><<<gE, 256, GEMM_SMEM>>>(t1, w2, out, b2, out, E_, F_);
}